// round 1
// baseline (speedup 1.0000x reference)
#include <cuda_runtime.h>
#include <math.h>

#define NN 100000
#define NE 1000000
#define D  64
#define H  128
#define NL 4
#define NG 64

// persistent scratch (device globals -- no allocation allowed)
__device__ float g_h[NN * D];        // node features
__device__ float g_PQ[NN * 256];     // P = h@W1[0:64] (cols 0..127), Q = h@W1[64:128] (cols 128..255)
__device__ float g_agg[NN * D];      // per-layer aggregation
__device__ float g_rbf[(size_t)NE * 16];
__device__ int   g_kind[NE];
__device__ float g_kt[NL * 2 * H];   // b1 + subunit_emb[kind]@W1[144:160]
__device__ float g_sums[NG * D];
__device__ float g_cnt[NG];

__global__ void k_init_h(const int* __restrict__ atoms, const float* __restrict__ embed) {
    int i = blockIdx.x * blockDim.x + threadIdx.x;
    if (i < NN * D) g_h[i] = embed[atoms[i >> 6] * D + (i & 63)];
}

__global__ void k_edge_prep(const int* __restrict__ ei, const float* __restrict__ coord,
                            const int* __restrict__ isr) {
    int e = blockIdx.x * blockDim.x + threadIdx.x;
    if (e >= NE) return;
    int s = ei[e], d = ei[NE + e];
    float dx = coord[s * 3 + 0] - coord[d * 3 + 0];
    float dy = coord[s * 3 + 1] - coord[d * 3 + 1];
    float dz = coord[s * 3 + 2] - coord[d * 3 + 2];
    float dist = sqrtf(dx * dx + dy * dy + dz * dz);
    const float coeff = -4.5f;  // -0.5 / (5/15)^2
    float o[16];
#pragma unroll
    for (int g = 0; g < 16; g++) {
        float t = dist - (float)g * (5.0f / 15.0f);
        o[g] = __expf(coeff * t * t);
    }
    float4* dp = (float4*)&g_rbf[(size_t)e * 16];
    dp[0] = make_float4(o[0], o[1], o[2], o[3]);
    dp[1] = make_float4(o[4], o[5], o[6], o[7]);
    dp[2] = make_float4(o[8], o[9], o[10], o[11]);
    dp[3] = make_float4(o[12], o[13], o[14], o[15]);
    g_kind[e] = (isr[s] != isr[d]) ? 1 : 0;
}

__global__ void k_kindtab(const float* __restrict__ subw, const float* __restrict__ W1,
                          const float* __restrict__ b1) {
    int t = blockIdx.x * blockDim.x + threadIdx.x;
    if (t >= NL * 2 * H) return;
    int l = t >> 8, kind = (t >> 7) & 1, j = t & 127;
    const float* W1l = W1 + (size_t)l * 160 * H;
    float v = b1[l * H + j];
#pragma unroll
    for (int g = 0; g < 16; g++)
        v += subw[kind * 16 + g] * W1l[(144 + g) * H + j];
    g_kt[t] = v;
}

__global__ void k_zero_agg() {
    int i = blockIdx.x * blockDim.x + threadIdx.x;
    if (i < NN * D) g_agg[i] = 0.f;
}

__global__ void k_zero_pool() {
    int i = blockIdx.x * blockDim.x + threadIdx.x;
    if (i < NG * D) g_sums[i] = 0.f;
    if (i < NG) g_cnt[i] = 0.f;
}

// P/Q node GEMM: PQ[n][j<128] = sum_k h[n][k] W1[k][j]; PQ[n][128+j] = sum_k h[n][k] W1[64+k][j]
__global__ __launch_bounds__(256) void k_nodegemm(const float* __restrict__ W1, int l) {
    __shared__ float sW[64 * H];     // 32 KB
    __shared__ float sh[64 * 17];    // h tile transposed, padded
    const float* W1l = W1 + (size_t)l * 160 * H;
    int tid = threadIdx.x;
    int n0 = blockIdx.x * 16;
    for (int i = tid; i < 16 * 64; i += 256) {
        int k = i & 63, e = i >> 6;
        sh[k * 17 + e] = g_h[(size_t)(n0 + e) * D + k];
    }
    int j = tid & 127;
    int ng = tid >> 7;  // node half (8 nodes each)
    for (int pass = 0; pass < 2; pass++) {
        __syncthreads();
        for (int i = tid; i < 64 * H; i += 256)
            sW[i] = W1l[pass * 64 * H + i];
        __syncthreads();
        float acc[8];
#pragma unroll
        for (int e = 0; e < 8; e++) acc[e] = 0.f;
#pragma unroll 8
        for (int k = 0; k < 64; k++) {
            float w = sW[k * H + j];
#pragma unroll
            for (int e = 0; e < 8; e++)
                acc[e] += sh[k * 17 + ng * 8 + e] * w;
        }
#pragma unroll
        for (int e = 0; e < 8; e++)
            g_PQ[(size_t)(n0 + ng * 8 + e) * 256 + pass * 128 + j] = acc[e];
    }
}

// fused edge kernel: pre-activation assembly + silu + GEMM2 + atomic scatter
// dyn smem layout (floats): W2 8192 | W1c 2048 | kt 256 | b2 64 | rbf 1024 | m1 128*68 | dst/src/kind 192
#define SM_TOTAL 20480
__global__ __launch_bounds__(256) void k_edge(const float* __restrict__ W1,
                                              const float* __restrict__ W2,
                                              const float* __restrict__ b2,
                                              const int* __restrict__ ei, int l) {
    extern __shared__ float sm[];
    float* sW2  = sm;            // [j*64+d]
    float* sW1c = sm + 8192;     // [g*128+j]
    float* sKt  = sm + 10240;    // [kind*128+j]
    float* sB2  = sm + 10496;
    float* sRbf = sm + 10560;    // [e*16+g]
    float* sM1  = sm + 11584;    // [j*68+e], pitch 68 (16B aligned rows)
    int* sDst   = (int*)(sm + 20288);
    int* sSrc   = (int*)(sm + 20352);
    int* sKind  = (int*)(sm + 20416);

    int tid = threadIdx.x;
    int e0 = blockIdx.x * 64;
    const float* W1l = W1 + (size_t)l * 160 * H;
    const float* W2l = W2 + (size_t)l * H * D;

    for (int i = tid; i < H * D; i += 256) sW2[i] = W2l[i];
    for (int i = tid; i < 16 * H; i += 256) sW1c[i] = W1l[128 * H + i];
    if (tid < 256) sKt[tid] = g_kt[l * 256 + tid];
    if (tid < 64) {
        sB2[tid] = b2[l * D + tid];
        sSrc[tid] = ei[e0 + tid];
        sDst[tid] = ei[NE + e0 + tid];
        sKind[tid] = g_kind[e0 + tid];
    }
    for (int i = tid; i < 64 * 16; i += 256) sRbf[i] = g_rbf[(size_t)e0 * 16 + i];
    __syncthreads();

    // Phase A: m1[e][j] = silu(P[dst][j] + Q[src][j] + kt[kind][j] + rbf[e].W1c[:,j])
    {
        int j = tid & 127;
        int eg = tid >> 7;  // edge half
        float w1c[16];
#pragma unroll
        for (int g = 0; g < 16; g++) w1c[g] = sW1c[g * H + j];
        float kt0 = sKt[j], kt1 = sKt[H + j];
#pragma unroll 4
        for (int ee = 0; ee < 32; ee++) {
            int e = eg * 32 + ee;
            int dn = sDst[e], sn = sSrc[e];
            float acc = g_PQ[(size_t)dn * 256 + j] + g_PQ[(size_t)sn * 256 + 128 + j];
            acc += sKind[e] ? kt1 : kt0;
#pragma unroll
            for (int g = 0; g < 16; g++)
                acc += sRbf[e * 16 + g] * w1c[g];
            // silu = x / (1 + exp(-x))
            float mval = __fdividef(acc, 1.f + __expf(-acc));
            sM1[j * 68 + e] = mval;
        }
    }
    __syncthreads();

    // Phase B: out[e][d] = b2[d] + sum_j m1[e][j]*W2[j][d]; atomicAdd to agg[dst]
    {
        int d = tid & 63;
        int g4 = tid >> 6;  // edge quarter
        int ebase = g4 * 16;
        float acc[16];
#pragma unroll
        for (int e = 0; e < 16; e++) acc[e] = 0.f;
#pragma unroll 2
        for (int j = 0; j < H; j++) {
            float w = sW2[j * D + d];
            const float4* row = (const float4*)&sM1[j * 68 + ebase];
            float4 a0 = row[0], a1 = row[1], a2 = row[2], a3 = row[3];
            acc[0]  += a0.x * w; acc[1]  += a0.y * w; acc[2]  += a0.z * w; acc[3]  += a0.w * w;
            acc[4]  += a1.x * w; acc[5]  += a1.y * w; acc[6]  += a1.z * w; acc[7]  += a1.w * w;
            acc[8]  += a2.x * w; acc[9]  += a2.y * w; acc[10] += a2.z * w; acc[11] += a2.w * w;
            acc[12] += a3.x * w; acc[13] += a3.y * w; acc[14] += a3.z * w; acc[15] += a3.w * w;
        }
        float bb = sB2[d];
#pragma unroll
        for (int e = 0; e < 16; e++)
            atomicAdd(&g_agg[(size_t)sDst[ebase + e] * D + d], acc[e] + bb);
    }
}

__global__ void k_relu() {
    int i = blockIdx.x * blockDim.x + threadIdx.x;
    if (i < NN * D) {
        g_h[i] = fmaxf(g_h[i] + g_agg[i], 0.f);
        g_agg[i] = 0.f;  // pre-zero for next layer
    }
}

__global__ void k_pool(const int* __restrict__ batch) {
    int i = blockIdx.x * blockDim.x + threadIdx.x;
    if (i >= NN * D) return;
    int n = i >> 6, d = i & 63;
    atomicAdd(&g_sums[batch[n] * D + d], g_h[i]);
}

__global__ void k_count(const int* __restrict__ batch) {
    int n = blockIdx.x * blockDim.x + threadIdx.x;
    if (n >= NN) return;
    int b = batch[n];
    unsigned mask = __activemask();
    unsigned m = __match_any_sync(mask, b);
    int leader = __ffs(m) - 1;
    if ((threadIdx.x & 31) == leader) atomicAdd(&g_cnt[b], (float)__popc(m));
}

__global__ void k_final(const float* __restrict__ fcw, const float* __restrict__ fcb,
                        float* __restrict__ out) {
    int g = threadIdx.x;
    if (g < NG) {
        float c = fmaxf(g_cnt[g], 1.f);
        float s = 0.f;
#pragma unroll
        for (int d = 0; d < D; d++) s += g_sums[g * D + d] * fcw[d];
        out[g] = s / c + fcb[0];
    }
}

extern "C" void kernel_launch(void* const* d_in, const int* in_sizes, int n_in,
                              void* d_out, int out_size) {
    const int*   atoms = (const int*)d_in[0];
    const int*   ei    = (const int*)d_in[1];
    const float* coord = (const float*)d_in[2];
    const int*   isr   = (const int*)d_in[3];
    const int*   batch = (const int*)d_in[4];
    const float* embed = (const float*)d_in[5];
    const float* subw  = (const float*)d_in[6];
    const float* W1    = (const float*)d_in[7];
    const float* b1    = (const float*)d_in[8];
    const float* W2    = (const float*)d_in[9];
    const float* b2    = (const float*)d_in[10];
    const float* fcw   = (const float*)d_in[11];
    const float* fcb   = (const float*)d_in[12];
    float* out = (float*)d_out;

    cudaFuncSetAttribute(k_edge, cudaFuncAttributeMaxDynamicSharedMemorySize, SM_TOTAL * 4);

    const int T = 256;
    k_init_h<<<(NN * D + T - 1) / T, T>>>(atoms, embed);
    k_edge_prep<<<(NE + T - 1) / T, T>>>(ei, coord, isr);
    k_kindtab<<<4, 256>>>(subw, W1, b1);
    k_zero_agg<<<(NN * D + T - 1) / T, T>>>();
    k_zero_pool<<<16, 256>>>();

    for (int l = 0; l < NL; l++) {
        k_nodegemm<<<NN / 16, 256>>>(W1, l);
        k_edge<<<NE / 64, 256, SM_TOTAL * 4>>>(W1, W2, b2, ei, l);
        k_relu<<<(NN * D + T - 1) / T, T>>>();
    }

    k_pool<<<(NN * D + T - 1) / T, T>>>(batch);
    k_count<<<(NN + T - 1) / T, T>>>(batch);
    k_final<<<1, 64>>>(fcw, fcb, out);
}

// round 3
// speedup vs baseline: 1.9865x; 1.9865x over previous
#include <cuda_runtime.h>
#include <cuda_bf16.h>
#include <math.h>
#include <stdint.h>

#define NN 100000
#define NE 1000000
#define D  64
#define H  128
#define NL 4
#define NG 64
#define TILE_E 128
#define NT ((NE + TILE_E - 1) / TILE_E)   // 7813
#define EGRID 148
#define ETHREADS 512

typedef unsigned long long ull;

// ---------------- persistent device scratch ----------------
__device__ float g_h[NN * D];
__device__ float g_PQ[NN * 256];     // P (cols 0..127) | Q (cols 128..255)
__device__ float g_agg[NN * D];
__device__ float g_rbf[(size_t)NE * 16];
__device__ int   g_kind[NE];
__device__ float g_kt[NL * 2 * H];
__device__ float g_sums[NG * D];
__device__ float g_cnt[NG];

// ---------------- f32x2 helpers ----------------
#define PACK2(d, x, y) asm("mov.b64 %0, {%1,%2};" : "=l"(d) : "r"(__float_as_uint(x)), "r"(__float_as_uint(y)))
#define UNPK2(lo, hi, v) asm("mov.b64 {%0,%1}, %2;" : "=r"(lo), "=r"(hi) : "l"(v))
#define FMA2(acc, a, b) asm("fma.rn.f32x2 %0, %1, %2, %0;" : "+l"(acc) : "l"(a), "l"(b))
#define ADD2(d, a, b)   asm("add.rn.f32x2 %0, %1, %2;" : "=l"(d) : "l"(a), "l"(b))
#define REDV4(p, v0, v1, v2, v3) \
    asm volatile("red.global.add.v4.f32 [%0], {%1,%2,%3,%4};" \
        :: "l"(p), "f"(v0), "f"(v1), "f"(v2), "f"(v3) : "memory")

// ---------------- small kernels ----------------
__global__ void k_init_h(const int* __restrict__ atoms, const float* __restrict__ embed) {
    int i = blockIdx.x * blockDim.x + threadIdx.x;
    if (i < NN * D) g_h[i] = embed[atoms[i >> 6] * D + (i & 63)];
}

__global__ void k_edge_prep(const int* __restrict__ ei, const float* __restrict__ coord,
                            const int* __restrict__ isr) {
    int e = blockIdx.x * blockDim.x + threadIdx.x;
    if (e >= NE) return;
    int s = ei[e], d = ei[NE + e];
    float dx = coord[s * 3 + 0] - coord[d * 3 + 0];
    float dy = coord[s * 3 + 1] - coord[d * 3 + 1];
    float dz = coord[s * 3 + 2] - coord[d * 3 + 2];
    float dist = sqrtf(dx * dx + dy * dy + dz * dz);
    const float coeff = -4.5f;
    float o[16];
#pragma unroll
    for (int g = 0; g < 16; g++) {
        float t = dist - (float)g * (5.0f / 15.0f);
        o[g] = __expf(coeff * t * t);
    }
    float4* dp = (float4*)&g_rbf[(size_t)e * 16];
    dp[0] = make_float4(o[0], o[1], o[2], o[3]);
    dp[1] = make_float4(o[4], o[5], o[6], o[7]);
    dp[2] = make_float4(o[8], o[9], o[10], o[11]);
    dp[3] = make_float4(o[12], o[13], o[14], o[15]);
    g_kind[e] = (isr[s] != isr[d]) ? 1 : 0;
}

__global__ void k_kindtab(const float* __restrict__ subw, const float* __restrict__ W1,
                          const float* __restrict__ b1) {
    int t = blockIdx.x * blockDim.x + threadIdx.x;
    if (t >= NL * 2 * H) return;
    int l = t >> 8, kind = (t >> 7) & 1, j = t & 127;
    const float* W1l = W1 + (size_t)l * 160 * H;
    float v = b1[l * H + j];
#pragma unroll
    for (int g = 0; g < 16; g++)
        v += subw[kind * 16 + g] * W1l[(144 + g) * H + j];
    g_kt[t] = v;
}

__global__ void k_zero_all() {
    int i = blockIdx.x * blockDim.x + threadIdx.x;
    if (i < NN * D) g_agg[i] = 0.f;
    if (i < NG * D) g_sums[i] = 0.f;
    if (i < NG) g_cnt[i] = 0.f;
}

// ---------------- node GEMM (f32x2 packed) ----------------
__global__ __launch_bounds__(256) void k_nodegemm(const float* __restrict__ W1, int l) {
    __shared__ float sW[64 * H];
    __shared__ float sh[64 * 18];
    const float* W1l = W1 + (size_t)l * 160 * H;
    int tid = threadIdx.x;
    int n0 = blockIdx.x * 16;
    for (int i = tid; i < 16 * 64; i += 256) {
        int k = i & 63, e = i >> 6;
        sh[k * 18 + e] = g_h[(size_t)(n0 + e) * D + k];
    }
    int j = tid & 127;
    int ng = tid >> 7;
    for (int pass = 0; pass < 2; pass++) {
        __syncthreads();
        for (int i = tid; i < 64 * H; i += 256) sW[i] = W1l[pass * 64 * H + i];
        __syncthreads();
        ull acc[4];
#pragma unroll
        for (int q = 0; q < 4; q++) acc[q] = 0ull;
#pragma unroll 8
        for (int k = 0; k < 64; k++) {
            float w = sW[k * H + j];
            ull ww; PACK2(ww, w, w);
#pragma unroll
            for (int q = 0; q < 4; q++) {
                ull hv = *(const ull*)&sh[k * 18 + ng * 8 + q * 2];
                FMA2(acc[q], hv, ww);
            }
        }
#pragma unroll
        for (int q = 0; q < 4; q++) {
            uint32_t lo, hi; UNPK2(lo, hi, acc[q]);
            int nb = n0 + ng * 8 + q * 2;
            g_PQ[(size_t)nb * 256 + pass * 128 + j] = __uint_as_float(lo);
            g_PQ[(size_t)(nb + 1) * 256 + pass * 128 + j] = __uint_as_float(hi);
        }
    }
}

// ---------------- fused persistent edge kernel ----------------
// smem byte offsets
#define M1_PITCH  132
#define OFF_W2    0                      // 128*64 f32 = 32768
#define OFF_M1    32768                  // 128*132*4 = 67584
#define OFF_W1C   100352                 // 16*128*4 = 8192
#define OFF_KT    108544                 // 1024
#define OFF_B2    109568                 // 256
#define OFF_RBF   109824                 // 128*16*4 = 8192
#define OFF_DST   118016                 // 512
#define OFF_SRC   118528                 // 512
#define OFF_KND   119040                 // 512
#define SMEM_EDGE 119552

__global__ __launch_bounds__(ETHREADS, 1) void k_edge(const float* __restrict__ W1,
                                                      const float* __restrict__ W2,
                                                      const float* __restrict__ b2,
                                                      const int* __restrict__ ei, int l) {
    extern __shared__ char smem[];
    float* sW2  = (float*)(smem + OFF_W2);
    float* sM1  = (float*)(smem + OFF_M1);
    float* sW1C = (float*)(smem + OFF_W1C);
    float* sKt  = (float*)(smem + OFF_KT);
    float* sB2  = (float*)(smem + OFF_B2);
    float* sRbf = (float*)(smem + OFF_RBF);
    int*   sDst = (int*)(smem + OFF_DST);
    int*   sSrc = (int*)(smem + OFF_SRC);
    int*   sKnd = (int*)(smem + OFF_KND);

    int tid = threadIdx.x;
    const float* W1l = W1 + (size_t)l * 160 * H;
    const float* W2l = W2 + (size_t)l * H * D;

    for (int i = tid; i < H * D; i += ETHREADS) sW2[i] = W2l[i];
    for (int i = tid; i < 16 * H; i += ETHREADS) sW1C[i] = W1l[128 * H + i];
    if (tid < 256) sKt[tid] = g_kt[l * 256 + tid];
    if (tid < 64) sB2[tid] = b2[l * D + tid];
    __syncthreads();

    // phase A thread mapping: cols (jp, jp+64); 8 edge groups of 16
    const int jp = tid & 63;
    const int egA = tid >> 6;
    // phase B mapping: 4 d x 4 edges
    const int dq = tid & 15;
    const int egB = tid >> 4;
    const int dbase = dq * 4;
    const int ebaseB = egB * 4;

    // hoisted per-layer constants (f32x2 over cols jp, jp+64)
    ull w1c2[16];
#pragma unroll
    for (int g = 0; g < 16; g++)
        PACK2(w1c2[g], sW1C[g * H + jp], sW1C[g * H + jp + 64]);
    ull ktv0, ktv1;
    PACK2(ktv0, sKt[jp], sKt[jp + 64]);
    PACK2(ktv1, sKt[H + jp], sKt[H + jp + 64]);

    const int chunk = (NT + EGRID - 1) / EGRID;
    int t0 = blockIdx.x * chunk;
    int t1 = t0 + chunk; if (t1 > NT) t1 = NT;

    for (int t = t0; t < t1; t++) {
        int e0 = t * TILE_E;
        // ---- tile metadata ----
        if (tid < TILE_E) {
            int e = e0 + tid;
            bool v = e < NE;
            sSrc[tid] = v ? ei[e] : 0;
            sDst[tid] = v ? ei[NE + e] : -1;
            sKnd[tid] = v ? g_kind[e] : 0;
        }
        {
            int i = tid;  // 512 float4 = 2048 floats
            int e = e0 + (i >> 2);
            ((float4*)sRbf)[i] = (e < NE) ? ((const float4*)g_rbf)[(size_t)t * 512 + i]
                                          : make_float4(0.f, 0.f, 0.f, 0.f);
        }
        __syncthreads();

        // ---- phase A: m1 = silu(P[dst]+Q[src]+kt[kind]+rbf@W1c) ----
#pragma unroll 2
        for (int ee = 0; ee < 16; ee += 2) {
            float res[2][2];  // [edge 0/1][col jp / jp+64]
#pragma unroll
            for (int u = 0; u < 2; u++) {
                int e = egA * 16 + ee + u;
                int dn = sDst[e];
                int sn = sSrc[e];
                int dnc = dn < 0 ? 0 : dn;
                const float* Pp = &g_PQ[(size_t)dnc * 256];
                const float* Qp = &g_PQ[(size_t)sn * 256 + 128];
                float p0 = Pp[jp], p1 = Pp[jp + 64];
                float q0 = Qp[jp], q1 = Qp[jp + 64];
                ull acc;
                PACK2(acc, p0 + q0, p1 + q1);
                ADD2(acc, acc, sKnd[e] ? ktv1 : ktv0);
                const float* rb = &sRbf[e * 16];
#pragma unroll
                for (int g = 0; g < 16; g++) {
                    float r = rb[g];
                    ull rr; PACK2(rr, r, r);
                    FMA2(acc, rr, w1c2[g]);
                }
                uint32_t xl, xh; UNPK2(xl, xh, acc);
                float x0 = __uint_as_float(xl), x1 = __uint_as_float(xh);
                res[u][0] = __fdividef(x0, 1.f + __expf(-x0));
                res[u][1] = __fdividef(x1, 1.f + __expf(-x1));
            }
            int e = egA * 16 + ee;
            *(float2*)&sM1[jp * M1_PITCH + e] = make_float2(res[0][0], res[1][0]);
            *(float2*)&sM1[(jp + 64) * M1_PITCH + e] = make_float2(res[0][1], res[1][1]);
        }
        __syncthreads();

        // ---- phase B: out[e][d] = b2 + sum_j m1[e][j] W2[j][d]; RED.v4 scatter ----
        {
            ull a01[4], a23[4];
#pragma unroll
            for (int d = 0; d < 4; d++) { a01[d] = 0ull; a23[d] = 0ull; }
#pragma unroll 4
            for (int j = 0; j < H; j++) {
                float4 wv = *(const float4*)&sW2[j * D + dbase];
                float4 mv = *(const float4*)&sM1[j * M1_PITCH + ebaseB];
                ull m01, m23;
                PACK2(m01, mv.x, mv.y);
                PACK2(m23, mv.z, mv.w);
                ull ww;
                PACK2(ww, wv.x, wv.x); FMA2(a01[0], m01, ww); FMA2(a23[0], m23, ww);
                PACK2(ww, wv.y, wv.y); FMA2(a01[1], m01, ww); FMA2(a23[1], m23, ww);
                PACK2(ww, wv.z, wv.z); FMA2(a01[2], m01, ww); FMA2(a23[2], m23, ww);
                PACK2(ww, wv.w, wv.w); FMA2(a01[3], m01, ww); FMA2(a23[3], m23, ww);
            }
            float v[4][4];  // [edge][d]
#pragma unroll
            for (int d = 0; d < 4; d++) {
                float bb = sB2[dbase + d];
                uint32_t lo, hi;
                UNPK2(lo, hi, a01[d]);
                v[0][d] = __uint_as_float(lo) + bb;
                v[1][d] = __uint_as_float(hi) + bb;
                UNPK2(lo, hi, a23[d]);
                v[2][d] = __uint_as_float(lo) + bb;
                v[3][d] = __uint_as_float(hi) + bb;
            }
#pragma unroll
            for (int k = 0; k < 4; k++) {
                int dn = sDst[ebaseB + k];
                if (dn >= 0) {
                    float* p = &g_agg[(size_t)dn * D + dbase];
                    REDV4(p, v[k][0], v[k][1], v[k][2], v[k][3]);
                }
            }
        }
        __syncthreads();
    }
}

__global__ void k_relu() {
    int i = blockIdx.x * blockDim.x + threadIdx.x;
    if (i < NN * D) {
        g_h[i] = fmaxf(g_h[i] + g_agg[i], 0.f);
        g_agg[i] = 0.f;
    }
}

__global__ void k_pool(const int* __restrict__ batch) {
    int i = blockIdx.x * blockDim.x + threadIdx.x;
    if (i >= NN * D) return;
    int n = i >> 6, d = i & 63;
    atomicAdd(&g_sums[batch[n] * D + d], g_h[i]);
}

__global__ void k_count(const int* __restrict__ batch) {
    int n = blockIdx.x * blockDim.x + threadIdx.x;
    if (n >= NN) return;
    int b = batch[n];
    unsigned mask = __activemask();
    unsigned m = __match_any_sync(mask, b);
    int leader = __ffs(m) - 1;
    if ((threadIdx.x & 31) == leader) atomicAdd(&g_cnt[b], (float)__popc(m));
}

__global__ void k_final(const float* __restrict__ fcw, const float* __restrict__ fcb,
                        float* __restrict__ out) {
    int g = threadIdx.x;
    if (g < NG) {
        float c = fmaxf(g_cnt[g], 1.f);
        float s = 0.f;
#pragma unroll
        for (int d = 0; d < D; d++) s += g_sums[g * D + d] * fcw[d];
        out[g] = s / c + fcb[0];
    }
}

extern "C" void kernel_launch(void* const* d_in, const int* in_sizes, int n_in,
                              void* d_out, int out_size) {
    const int*   atoms = (const int*)d_in[0];
    const int*   ei    = (const int*)d_in[1];
    const float* coord = (const float*)d_in[2];
    const int*   isr   = (const int*)d_in[3];
    const int*   batch = (const int*)d_in[4];
    const float* embed = (const float*)d_in[5];
    const float* subw  = (const float*)d_in[6];
    const float* W1    = (const float*)d_in[7];
    const float* b1    = (const float*)d_in[8];
    const float* W2    = (const float*)d_in[9];
    const float* b2    = (const float*)d_in[10];
    const float* fcw   = (const float*)d_in[11];
    const float* fcb   = (const float*)d_in[12];
    float* out = (float*)d_out;

    cudaFuncSetAttribute(k_edge, cudaFuncAttributeMaxDynamicSharedMemorySize, SMEM_EDGE);

    const int T = 256;
    k_init_h<<<(NN * D + T - 1) / T, T>>>(atoms, embed);
    k_edge_prep<<<(NE + T - 1) / T, T>>>(ei, coord, isr);
    k_kindtab<<<4, 256>>>(subw, W1, b1);
    k_zero_all<<<(NN * D + T - 1) / T, T>>>();

    for (int l = 0; l < NL; l++) {
        k_nodegemm<<<NN / 16, 256>>>(W1, l);
        k_edge<<<EGRID, ETHREADS, SMEM_EDGE>>>(W1, W2, b2, ei, l);
        k_relu<<<(NN * D + T - 1) / T, T>>>();
    }

    k_pool<<<(NN * D + T - 1) / T, T>>>(batch);
    k_count<<<(NN + T - 1) / T, T>>>(batch);
    k_final<<<1, 64>>>(fcw, fcb, out);
}